// round 10
// baseline (speedup 1.0000x reference)
#include <cuda_runtime.h>
#include <math.h>

#define Nb   8
#define NRr  300
#define Dd   256
#define Hh   8
#define Ss   49
#define DDd  64
#define FFf  2048
#define NCc  80
#define MTOT (Nb*NRr)          // 2400
#define PAR  32768             // 2*D*DD
#define QT   8

// ---------------- scratch (device globals; no allocation allowed) ----------------
__device__ float g_qk  [MTOT*Dd];
__device__ float g_qkp [MTOT*512];
__device__ float g_vp  [MTOT*Dd];
__device__ float g_ctx [MTOT*Dd];
__device__ float g_pf1 [MTOT*Dd];
__device__ float g_pfB [MTOT*Dd];
__device__ float g_clsf[MTOT*Dd];
__device__ float g_obj [MTOT*Dd];
__device__ float g_ffh [MTOT*FFf];
__device__ unsigned g_pf1t[MTOT*Dd];
__device__ unsigned g_pfBt[MTOT*Dd];
__device__ float g_params[(size_t)MTOT*PAR];       // 314 MB (tf32-rounded values)
__device__ float g_f2  [(size_t)MTOT*Ss*Dd];       // 120 MB (tf32-rounded values)
__device__ float g_part[(size_t)8*MTOT*Dd];
__device__ unsigned char g_maskb[Nb*NRr*NRr];
// pre-converted big weights (tf32 bits)
#define OFF_WDYN 0
#define OFF_WDO  (OFF_WDYN + PAR*Dd)          //  8388608
#define OFF_WFF1 (OFF_WDO  + Dd*Ss*Dd)        // 11599872
#define OFF_WFF2 (OFF_WFF1 + FFf*Dd)          // 12124160
#define WC_TOTAL (OFF_WFF2 + Dd*FFf)          // 12648448 words
__device__ unsigned g_wc[WC_TOTAL];

// ---------------- helpers ----------------
__device__ __forceinline__ unsigned f2tf(float x) {
    unsigned u;
    asm("cvt.rna.tf32.f32 %0, %1;" : "=r"(u) : "f"(x));
    return u;
}

__device__ __forceinline__ void mma_tf32(float* d, const unsigned* a, const unsigned* b) {
    asm volatile("mma.sync.aligned.m16n8k8.row.col.f32.tf32.tf32.f32 "
                 "{%0,%1,%2,%3}, {%4,%5,%6,%7}, {%8,%9}, {%0,%1,%2,%3};"
                 : "+f"(d[0]), "+f"(d[1]), "+f"(d[2]), "+f"(d[3])
                 : "r"(a[0]), "r"(a[1]), "r"(a[2]), "r"(a[3]), "r"(b[0]), "r"(b[1]));
}

__device__ __forceinline__ void cpa16(void* smem, const void* g, int sz) {
    unsigned d = (unsigned)__cvta_generic_to_shared(smem);
    asm volatile("cp.async.cg.shared.global [%0], [%1], 16, %2;" :: "r"(d), "l"(g), "r"(sz));
}

__device__ __forceinline__ float blockSum256(float v, float* red) {
#pragma unroll
    for (int o = 16; o; o >>= 1) v += __shfl_down_sync(0xffffffffu, v, o);
    if ((threadIdx.x & 31) == 0) red[threadIdx.x >> 5] = v;
    __syncthreads();
    float s = red[0]+red[1]+red[2]+red[3]+red[4]+red[5]+red[6]+red[7];
    __syncthreads();
    return s;
}

// ---------------- weight pre-round (tf32 bits) ----------------
struct WJobs { const float* s[4]; unsigned* d[4]; int n[4]; };
__global__ void wcvt_kernel(WJobs j)
{
    int stride = gridDim.x * blockDim.x;
    int base = blockIdx.x * blockDim.x + threadIdx.x;
#pragma unroll
    for (int q = 0; q < 4; ++q) {
        int n4 = j.n[q] >> 2;
        const float4* s4 = (const float4*)j.s[q];
        uint4* d4 = (uint4*)j.d[q];
        for (int i = base; i < n4; i += stride) {
            float4 v = s4[i];
            uint4 o;
            o.x = f2tf(v.x); o.y = f2tf(v.y); o.z = f2tf(v.z); o.w = f2tf(v.w);
            d4[i] = o;
        }
    }
}

// ---------------- merged: IoU mask + (pro+query) add ----------------
__global__ void init_kernel(const float* __restrict__ bb, const float* __restrict__ cm,
                            unsigned char* __restrict__ mask,
                            const float* __restrict__ pro, const float* __restrict__ query,
                            float* __restrict__ qkout)
{
    int idx = blockIdx.x * blockDim.x + threadIdx.x;
    if (idx < MTOT*Dd) qkout[idx] = pro[idx] + query[idx];
    if (idx < Nb*NRr*NRr) {
        int b = idx / (NRr*NRr);
        int r = idx - b*NRr*NRr;
        int q = r / NRr, k = r - q*NRr;
        const float* bq = bb + (size_t)(b*NRr+q)*4;
        const float* bk = bb + (size_t)(b*NRr+k)*4;
        float areaA = (bq[2]-bq[0])*(bq[3]-bq[1]);
        float areaB = (bk[2]-bk[0])*(bk[3]-bk[1]);
        float ix = fmaxf(fminf(bq[2],bk[2]) - fmaxf(bq[0],bk[0]), 0.f);
        float iy = fmaxf(fminf(bq[3],bk[3]) - fmaxf(bq[1],bk[1]), 0.f);
        float inter = ix*iy;
        float iou = inter / fmaxf(areaA + areaB - inter, 1e-9f);
        float cq = cm[b*NRr+q], ck = cm[b*NRr+k];
        float omask = (iou < 0.5f) ? 1.f : 0.f;
        float val = omask*cq*ck + ((q==k) ? (1.f-cq) : 0.f);
        mask[idx] = (val > 0.f) ? (unsigned char)1 : (unsigned char)0;
    }
}

// ================= tf32 tensor-core GEMM, 2-stage double-buffered ==============
// C = A[M,K] @ W[N,K]^T (+bias). flags: bit0 relu, bit1 tf32-round output.
// PC=1: A and W already hold tf32 bit patterns; skip inner cvt (bit-identical).
template<int MT, int PC>
__global__ void __launch_bounds__(256) gemm_tc(
    const float* __restrict__ A, const float* __restrict__ W,
    const float* __restrict__ bias, float* __restrict__ C,
    int M, int N, int K, int flags)
{
    constexpr int BMt = 64*MT;
    __shared__ unsigned As[2][BMt][20];
    __shared__ unsigned Bs[2][64][20];
    int tid  = threadIdx.x;
    int lane = tid & 31;
    int warp = tid >> 5;
    int rowBase = blockIdx.y * BMt;
    int colBase = blockIdx.x * 64;
    int kc   = K / gridDim.z;
    int kbeg = blockIdx.z * kc;
    float* Cp = C + (size_t)blockIdx.z * (size_t)M * (size_t)N;

    int mBase = (warp >> 1) * 16 * MT;
    int nBase = (warp & 1) * 32;
    int gr = lane >> 2, gc = lane & 3;

    float acc[MT][4][4];
#pragma unroll
    for (int a_ = 0; a_ < MT; ++a_)
#pragma unroll
        for (int b_ = 0; b_ < 4; ++b_)
#pragma unroll
            for (int c_ = 0; c_ < 4; ++c_) acc[a_][b_][c_] = 0.f;

    int ar[MT], ak[MT];
#pragma unroll
    for (int c = 0; c < MT; ++c) { int u = tid + c*256; ar[c] = u >> 2; ak[c] = (u & 3) * 4; }
    int br = tid >> 2, bk = (tid & 3) * 4;

    int nIter = kc / 16;

    {
#pragma unroll
        for (int c = 0; c < MT; ++c) {
            int r = rowBase + ar[c];
            int rc = (r < M) ? r : (M - 1);
            cpa16(&As[0][ar[c]][ak[c]], A + (size_t)rc*K + kbeg + ak[c], (r < M) ? 16 : 0);
        }
        int n = colBase + br;
        int ncl = (n < N) ? n : (N - 1);
        cpa16(&Bs[0][br][bk], W + (size_t)ncl*K + kbeg + bk, (n < N) ? 16 : 0);
        asm volatile("cp.async.commit_group;");
    }

    for (int i = 0; i < nIter; ++i) {
        if (i + 1 < nIter) {
            int k0 = kbeg + (i+1)*16;
            int nb = (i+1) & 1;
#pragma unroll
            for (int c = 0; c < MT; ++c) {
                int r = rowBase + ar[c];
                int rc = (r < M) ? r : (M - 1);
                cpa16(&As[nb][ar[c]][ak[c]], A + (size_t)rc*K + k0 + ak[c], (r < M) ? 16 : 0);
            }
            int n = colBase + br;
            int ncl = (n < N) ? n : (N - 1);
            cpa16(&Bs[nb][br][bk], W + (size_t)ncl*K + k0 + bk, (n < N) ? 16 : 0);
            asm volatile("cp.async.commit_group;");
            asm volatile("cp.async.wait_group 1;");
        } else {
            asm volatile("cp.async.wait_group 0;");
        }
        __syncthreads();
        int buf = i & 1;
#pragma unroll
        for (int ks = 0; ks < 16; ks += 8) {
            unsigned a[MT][4], b[4][2];
#pragma unroll
            for (int mt = 0; mt < MT; ++mt) {
                int row = mBase + mt*16;
                if (PC) {
                    a[mt][0] = As[buf][row+gr  ][ks+gc  ];
                    a[mt][1] = As[buf][row+gr+8][ks+gc  ];
                    a[mt][2] = As[buf][row+gr  ][ks+4+gc];
                    a[mt][3] = As[buf][row+gr+8][ks+4+gc];
                } else {
                    a[mt][0] = f2tf(__uint_as_float(As[buf][row+gr  ][ks+gc  ]));
                    a[mt][1] = f2tf(__uint_as_float(As[buf][row+gr+8][ks+gc  ]));
                    a[mt][2] = f2tf(__uint_as_float(As[buf][row+gr  ][ks+4+gc]));
                    a[mt][3] = f2tf(__uint_as_float(As[buf][row+gr+8][ks+4+gc]));
                }
            }
#pragma unroll
            for (int nt = 0; nt < 4; ++nt) {
                int col = nBase + nt*8;
                if (PC) {
                    b[nt][0] = Bs[buf][col+gr][ks+gc  ];
                    b[nt][1] = Bs[buf][col+gr][ks+4+gc];
                } else {
                    b[nt][0] = f2tf(__uint_as_float(Bs[buf][col+gr][ks+gc  ]));
                    b[nt][1] = f2tf(__uint_as_float(Bs[buf][col+gr][ks+4+gc]));
                }
            }
#pragma unroll
            for (int mt = 0; mt < MT; ++mt)
#pragma unroll
                for (int nt = 0; nt < 4; ++nt)
                    mma_tf32(acc[mt][nt], a[mt], b[nt]);
        }
        __syncthreads();
    }

    int doRelu = flags & 1, doTf = flags & 2;
#pragma unroll
    for (int mt = 0; mt < MT; ++mt) {
#pragma unroll
        for (int nt = 0; nt < 4; ++nt) {
            int c = colBase + nBase + nt*8 + gc*2;
            if (c >= N) continue;
            float bx = bias ? bias[c]   : 0.f;
            float by = bias ? bias[c+1] : 0.f;
#pragma unroll
            for (int h = 0; h < 2; ++h) {
                int r = rowBase + mBase + mt*16 + gr + h*8;
                if (r >= M) continue;
                float x = acc[mt][nt][h*2+0] + bx, y = acc[mt][nt][h*2+1] + by;
                if (doRelu) { x = fmaxf(x,0.f); y = fmaxf(y,0.f); }
                if (doTf) { x = __uint_as_float(f2tf(x)); y = __uint_as_float(f2tf(y)); }
                *(float2*)(Cp + (size_t)r*N + c) = make_float2(x, y);
            }
        }
    }
}

// ---------------- masked MHSA: 8 queries per block, warp = head (R7 version) -----
#define ATTN_SMEM ((QT*256 + Hh*QT*NRr) * 4)
__global__ void __launch_bounds__(256) attn_kernel(
    const float* __restrict__ qkp, const float* __restrict__ vp,
    const unsigned char* __restrict__ mask, float* __restrict__ ctx)
{
    extern __shared__ float smf[];
    float* sq = smf;
    float* sc = smf + QT*256;
    int b  = blockIdx.y;
    int q0 = blockIdx.x * QT;
    int tid = threadIdx.x, w = tid >> 5, lane = tid & 31;

#pragma unroll
    for (int j = 0; j < QT; ++j) {
        int q = q0 + j; if (q >= NRr) q = NRr - 1;
        sq[j*256 + tid] = qkp[(size_t)(b*NRr + q)*512 + tid];
    }
    __syncthreads();

    const float scale = 0.17677669529663687f;
    float* scw = sc + w*QT*NRr;
    const unsigned char* mbase = mask + (size_t)b*NRr*NRr;

    for (int k = lane; k < NRr; k += 32) {
        const float4* kr = (const float4*)(qkp + ((size_t)(b*NRr + k))*512 + 256 + w*32);
        float4 kv[8];
#pragma unroll
        for (int u = 0; u < 8; ++u) kv[u] = kr[u];
#pragma unroll
        for (int j = 0; j < QT; ++j) {
            const float* sqr = sq + j*256 + w*32;
            float s = 0.f;
#pragma unroll
            for (int u = 0; u < 8; ++u)
                s += sqr[u*4+0]*kv[u].x + sqr[u*4+1]*kv[u].y + sqr[u*4+2]*kv[u].z + sqr[u*4+3]*kv[u].w;
            s *= scale;
            int q = q0 + j;
            if (q < NRr && mbase[(size_t)q*NRr + k]) s = -1e9f;
            scw[j*NRr + k] = s;
        }
    }
    __syncwarp();

    float inv[QT];
#pragma unroll
    for (int j = 0; j < QT; ++j) {
        float mx = -1e30f;
        for (int k = lane; k < NRr; k += 32) mx = fmaxf(mx, scw[j*NRr + k]);
#pragma unroll
        for (int o = 16; o; o >>= 1) mx = fmaxf(mx, __shfl_xor_sync(0xffffffffu, mx, o));
        float sum = 0.f;
        for (int k = lane; k < NRr; k += 32) {
            float e = expf(scw[j*NRr + k] - mx);
            scw[j*NRr + k] = e;
            sum += e;
        }
#pragma unroll
        for (int o = 16; o; o >>= 1) sum += __shfl_xor_sync(0xffffffffu, sum, o);
        inv[j] = 1.f / sum;
    }
    __syncwarp();

    float acc[QT];
#pragma unroll
    for (int j = 0; j < QT; ++j) acc[j] = 0.f;
#pragma unroll 4
    for (int k = 0; k < NRr; ++k) {
        float vv = vp[((size_t)(b*NRr + k))*Dd + w*32 + lane];
#pragma unroll
        for (int j = 0; j < QT; ++j) acc[j] += scw[j*NRr + k] * vv;
    }
#pragma unroll
    for (int j = 0; j < QT; ++j) {
        int q = q0 + j;
        if (q < NRr) ctx[(size_t)(b*NRr + q)*Dd + w*32 + lane] = acc[j] * inv[j];
    }
}

// ---------------- LayerNorm (D=256); X may be nz split-K slices; dual output -----
__global__ void ln_kernel(const float* __restrict__ X, int nz, const float* __restrict__ bias,
                          const float* __restrict__ R, const float* __restrict__ mrow,
                          float* __restrict__ out, unsigned* __restrict__ outTf, int doRelu)
{
    __shared__ float red[8];
    int i = blockIdx.x, t = threadIdx.x;
    float x = X[(size_t)i*Dd + t];
    for (int z = 1; z < nz; ++z) x += X[(size_t)z*MTOT*Dd + (size_t)i*Dd + t];
    if (bias) x += bias[t];
    if (R) x += R[(size_t)i*Dd + t];
    float m  = blockSum256(x, red) * (1.f/Dd);
    float dv = x - m;
    float var = blockSum256(dv*dv, red) * (1.f/Dd);
    float y = dv * rsqrtf(var + 1e-5f);
    if (doRelu) y = fmaxf(y, 0.f);
    if (mrow) y *= mrow[i];
    if (out)   out[(size_t)i*Dd + t] = y;
    if (outTf) outTf[(size_t)i*Dd + t] = f2tf(y);
}

// ---------------- double LN; dual output ----------
__global__ void ln2_kernel(const float* __restrict__ X, int nz, const float* __restrict__ bias,
                           const float* __restrict__ P,
                           float* __restrict__ out, unsigned* __restrict__ outTf)
{
    __shared__ float red[8];
    int i = blockIdx.x, t = threadIdx.x;
    float x = X[(size_t)i*Dd + t];
    for (int z = 1; z < nz; ++z) x += X[(size_t)z*MTOT*Dd + (size_t)i*Dd + t];
    if (bias) x += bias[t];
    float m  = blockSum256(x, red) * (1.f/Dd);
    float dv = x - m;
    float var = blockSum256(dv*dv, red) * (1.f/Dd);
    float y = fmaxf(dv * rsqrtf(var + 1e-5f), 0.f);
    float z2 = y + P[(size_t)i*Dd + t];
    m  = blockSum256(z2, red) * (1.f/Dd);
    dv = z2 - m;
    var = blockSum256(dv*dv, red) * (1.f/Dd);
    float o = dv * rsqrtf(var + 1e-5f);
    if (out)   out[(size_t)i*Dd + t] = o;
    if (outTf) outTf[(size_t)i*Dd + t] = f2tf(o);
}

// ================= DynamicConv v2 (R7 version; f2 rounded at write) ==============
#define DC_U    0
#define DC_F1   4608
#define DC_F2R  (DC_F1 + 4608)
#define DC_WORDS (DC_F2R + 49*264)

__global__ void __launch_bounds__(128) dynconv_tc(
    const float* __restrict__ roi, const float* __restrict__ params,
    float* __restrict__ f2out)
{
    extern __shared__ unsigned sm[];
    unsigned* Asm = sm + DC_U;
    unsigned* Bsm = sm + DC_U + 32*72;
    unsigned* Bs2 = sm + DC_U;
    unsigned* f1t = sm + DC_F1;
    float*    f2r = (float*)(sm + DC_F2R);

    int i    = blockIdx.x;
    int tid  = threadIdx.x;
    int lane = tid & 31;
    int warp = tid >> 5;
    int gr = lane >> 2, gc = lane & 3;
    int rowW = warp * 16;

    const float* p1 = params + (size_t)i * PAR;
    const float* p2 = p1 + Dd*DDd;

    int sA = tid >> 3;
    int d4A = (tid & 7) * 4;
    int dB = tid >> 4;
    int e4B = (tid & 15) * 4;

    float4 rA[4]; float4 rB[4];
#pragma unroll
    for (int p = 0; p < 4; ++p) {
        int s = p*16 + sA;
        rA[p] = (s < Ss) ? *(const float4*)(roi + ((size_t)s*MTOT + i)*Dd + 0 + d4A)
                         : make_float4(0.f,0.f,0.f,0.f);
        rB[p] = *(const float4*)(p1 + (size_t)(0 + p*8 + dB)*DDd + e4B);
    }

    float acc1[8][4];
#pragma unroll
    for (int a_ = 0; a_ < 8; ++a_)
#pragma unroll
        for (int c_ = 0; c_ < 4; ++c_) acc1[a_][c_] = 0.f;

    for (int dc = 0; dc < Dd; dc += 32) {
        __syncthreads();
#pragma unroll
        for (int p = 0; p < 4; ++p) {
            Asm[(d4A+0)*72 + p*16+sA] = f2tf(rA[p].x);
            Asm[(d4A+1)*72 + p*16+sA] = f2tf(rA[p].y);
            Asm[(d4A+2)*72 + p*16+sA] = f2tf(rA[p].z);
            Asm[(d4A+3)*72 + p*16+sA] = f2tf(rA[p].w);
            int d = p*8 + dB;
            Bsm[d*72 + e4B+0] = f2tf(rB[p].x);
            Bsm[d*72 + e4B+1] = f2tf(rB[p].y);
            Bsm[d*72 + e4B+2] = f2tf(rB[p].z);
            Bsm[d*72 + e4B+3] = f2tf(rB[p].w);
        }
        __syncthreads();
        if (dc + 32 < Dd) {
            int dn = dc + 32;
#pragma unroll
            for (int p = 0; p < 4; ++p) {
                int s = p*16 + sA;
                rA[p] = (s < Ss) ? *(const float4*)(roi + ((size_t)s*MTOT + i)*Dd + dn + d4A)
                                 : make_float4(0.f,0.f,0.f,0.f);
                rB[p] = *(const float4*)(p1 + (size_t)(dn + p*8 + dB)*DDd + e4B);
            }
        }
#pragma unroll
        for (int ks = 0; ks < 32; ks += 8) {
            unsigned a[4], b[8][2];
            a[0] = Asm[(ks+gc  )*72 + rowW+gr  ];
            a[1] = Asm[(ks+gc  )*72 + rowW+gr+8];
            a[2] = Asm[(ks+4+gc)*72 + rowW+gr  ];
            a[3] = Asm[(ks+4+gc)*72 + rowW+gr+8];
#pragma unroll
            for (int nt = 0; nt < 8; ++nt) {
                b[nt][0] = Bsm[(ks+gc  )*72 + nt*8+gr];
                b[nt][1] = Bsm[(ks+4+gc)*72 + nt*8+gr];
            }
#pragma unroll
            for (int nt = 0; nt < 8; ++nt) mma_tf32(acc1[nt], a, b[nt]);
        }
    }
    {
        float s0 = 0.f, s1 = 0.f;
#pragma unroll
        for (int nt = 0; nt < 8; ++nt) { s0 += acc1[nt][0]+acc1[nt][1]; s1 += acc1[nt][2]+acc1[nt][3]; }
        s0 += __shfl_xor_sync(0xffffffffu, s0, 1); s0 += __shfl_xor_sync(0xffffffffu, s0, 2);
        s1 += __shfl_xor_sync(0xffffffffu, s1, 1); s1 += __shfl_xor_sync(0xffffffffu, s1, 2);
        float m0 = s0 * (1.f/DDd), m1 = s1 * (1.f/DDd);
        float v0 = 0.f, v1 = 0.f;
#pragma unroll
        for (int nt = 0; nt < 8; ++nt) {
            float d0 = acc1[nt][0]-m0, d1 = acc1[nt][1]-m0;
            float d2 = acc1[nt][2]-m1, d3 = acc1[nt][3]-m1;
            v0 += d0*d0 + d1*d1; v1 += d2*d2 + d3*d3;
        }
        v0 += __shfl_xor_sync(0xffffffffu, v0, 1); v0 += __shfl_xor_sync(0xffffffffu, v0, 2);
        v1 += __shfl_xor_sync(0xffffffffu, v1, 1); v1 += __shfl_xor_sync(0xffffffffu, v1, 2);
        float r0f = rsqrtf(v0*(1.f/DDd) + 1e-5f);
        float r1f = rsqrtf(v1*(1.f/DDd) + 1e-5f);
        int sr0 = rowW + gr, sr1 = sr0 + 8;
#pragma unroll
        for (int nt = 0; nt < 8; ++nt) {
            int e = nt*8 + gc*2;
            f1t[(e  )*72 + sr0] = f2tf(fmaxf((acc1[nt][0]-m0)*r0f, 0.f));
            f1t[(e+1)*72 + sr0] = f2tf(fmaxf((acc1[nt][1]-m0)*r0f, 0.f));
            f1t[(e  )*72 + sr1] = f2tf(fmaxf((acc1[nt][2]-m1)*r1f, 0.f));
            f1t[(e+1)*72 + sr1] = f2tf(fmaxf((acc1[nt][3]-m1)*r1f, 0.f));
        }
    }

    float4 rC[8];
#pragma unroll
    for (int p = 0; p < 8; ++p)
        rC[p] = *(const float4*)(p2 + (size_t)(p*8 + dB)*Dd + 0 + e4B);

    for (int nc = 0; nc < Dd; nc += 64) {
        __syncthreads();
#pragma unroll
        for (int p = 0; p < 8; ++p) {
            int e = p*8 + dB;
            Bs2[e*72 + e4B+0] = f2tf(rC[p].x);
            Bs2[e*72 + e4B+1] = f2tf(rC[p].y);
            Bs2[e*72 + e4B+2] = f2tf(rC[p].z);
            Bs2[e*72 + e4B+3] = f2tf(rC[p].w);
        }
        __syncthreads();
        if (nc + 64 < Dd) {
            int nn = nc + 64;
#pragma unroll
            for (int p = 0; p < 8; ++p)
                rC[p] = *(const float4*)(p2 + (size_t)(p*8 + dB)*Dd + nn + e4B);
        }
        float acc2[8][4];
#pragma unroll
        for (int a_ = 0; a_ < 8; ++a_)
#pragma unroll
            for (int c_ = 0; c_ < 4; ++c_) acc2[a_][c_] = 0.f;
#pragma unroll
        for (int ks = 0; ks < 64; ks += 8) {
            unsigned a[4], b[8][2];
            a[0] = f1t[(ks+gc  )*72 + rowW+gr  ];
            a[1] = f1t[(ks+gc  )*72 + rowW+gr+8];
            a[2] = f1t[(ks+4+gc)*72 + rowW+gr  ];
            a[3] = f1t[(ks+4+gc)*72 + rowW+gr+8];
#pragma unroll
            for (int nt = 0; nt < 8; ++nt) {
                b[nt][0] = Bs2[(ks+gc  )*72 + nt*8+gr];
                b[nt][1] = Bs2[(ks+4+gc)*72 + nt*8+gr];
            }
#pragma unroll
            for (int nt = 0; nt < 8; ++nt) mma_tf32(acc2[nt], a, b[nt]);
        }
        int sr0 = rowW + gr, sr1 = sr0 + 8;
#pragma unroll
        for (int nt = 0; nt < 8; ++nt) {
            int c = nc + nt*8 + gc*2;
            if (sr0 < Ss) *(float2*)(f2r + sr0*264 + c) = make_float2(acc2[nt][0], acc2[nt][1]);
            if (sr1 < Ss) *(float2*)(f2r + sr1*264 + c) = make_float2(acc2[nt][2], acc2[nt][3]);
        }
    }
    __syncthreads();

    for (int s = warp; s < Ss; s += 4) {
        float v[8];
        float sum = 0.f;
#pragma unroll
        for (int j = 0; j < 8; ++j) { v[j] = f2r[s*264 + lane + 32*j]; sum += v[j]; }
#pragma unroll
        for (int o = 16; o; o >>= 1) sum += __shfl_xor_sync(0xffffffffu, sum, o);
        float m = sum * (1.f/Dd);
        float var = 0.f;
#pragma unroll
        for (int j = 0; j < 8; ++j) { float d = v[j]-m; var += d*d; }
#pragma unroll
        for (int o = 16; o; o >>= 1) var += __shfl_xor_sync(0xffffffffu, var, o);
        float rs = rsqrtf(var*(1.f/Dd) + 1e-5f);
        float* op = f2out + ((size_t)i*Ss + s)*Dd;
#pragma unroll
        for (int j = 0; j < 8; ++j)
            op[lane + 32*j] = __uint_as_float(f2tf(fmaxf((v[j]-m)*rs, 0.f)));  // rounded for PRECVT GEMM (idempotent)
    }
}

// ---------------- host side ----------------
static void* symaddr_(const void* sym) { void* p = nullptr; cudaGetSymbolAddress(&p, sym); return p; }
#define SYMF(x)  ((float*)symaddr_(x))
#define SYMU(x)  ((unsigned*)symaddr_(x))

extern "C" void kernel_launch(void* const* d_in, const int* in_sizes, int n_in,
                              void* d_out, int out_size)
{
    const float* bboxes = (const float*)d_in[0];
    const float* pro    = (const float*)d_in[1];
    const float* roi    = (const float*)d_in[2];
    const float* query  = (const float*)d_in[3];
    const float* cm     = (const float*)d_in[4];
    const float* w_qkv  = (const float*)d_in[5];
    const float* b_qkv  = (const float*)d_in[6];
    const float* w_ao   = (const float*)d_in[7];
    const float* b_ao   = (const float*)d_in[8];
    const float* w_dyn  = (const float*)d_in[9];
    const float* b_dyn  = (const float*)d_in[10];
    const float* w_do   = (const float*)d_in[11];
    const float* b_do   = (const float*)d_in[12];
    const float* w_ff1  = (const float*)d_in[13];
    const float* b_ff1  = (const float*)d_in[14];
    const float* w_ff2  = (const float*)d_in[15];
    const float* b_ff2  = (const float*)d_in[16];
    const float* w_cls  = (const float*)d_in[17];
    const float* w_lg   = (const float*)d_in[18];
    const float* b_lg   = (const float*)d_in[19];
    float* out = (float*)d_out;

    float* p_qk   = SYMF(g_qk);
    float* p_qkp  = SYMF(g_qkp);
    float* p_vp   = SYMF(g_vp);
    float* p_ctx  = SYMF(g_ctx);
    float* p_pf1  = SYMF(g_pf1);
    float* p_pfB  = SYMF(g_pfB);
    float* p_obj  = SYMF(g_obj);
    float* p_clsf = SYMF(g_clsf);
    float* p_ffh  = SYMF(g_ffh);
    float* p_par  = SYMF(g_params);
    float* p_f2   = SYMF(g_f2);
    float* p_part = SYMF(g_part);
    unsigned* p_pf1t = SYMU(g_pf1t);
    unsigned* p_pfBt = SYMU(g_pfBt);
    unsigned* p_wc   = SYMU(g_wc);
    unsigned char* p_mask = (unsigned char*)symaddr_(g_maskb);

    static int smem_set = 0;
    if (!smem_set) {
        cudaFuncSetAttribute(dynconv_tc, cudaFuncAttributeMaxDynamicSharedMemorySize, DC_WORDS * 4);
        cudaFuncSetAttribute(attn_kernel, cudaFuncAttributeMaxDynamicSharedMemorySize, ATTN_SMEM);
        smem_set = 1;
    }

    const int MB128 = (MTOT + 127) / 128;   // 19
    const int MB64  = (MTOT + 63) / 64;     // 38

    // 0. pre-round big weights to tf32 bits (~50 MB, DRAM-bound ~15 µs)
    {
        WJobs j;
        j.s[0]=w_dyn; j.d[0]=p_wc+OFF_WDYN; j.n[0]=PAR*Dd;
        j.s[1]=w_do;  j.d[1]=p_wc+OFF_WDO;  j.n[1]=Dd*Ss*Dd;
        j.s[2]=w_ff1; j.d[2]=p_wc+OFF_WFF1; j.n[2]=FFf*Dd;
        j.s[3]=w_ff2; j.d[3]=p_wc+OFF_WFF2; j.n[3]=Dd*FFf;
        wcvt_kernel<<<1184, 256>>>(j);
    }
    // 1. IoU mask + (pro+query) merged
    init_kernel<<<(Nb*NRr*NRr + 255)/256, 256>>>(bboxes, cm, p_mask, pro, query, p_qk);
    // 2. merged Q|K projection (N=512) and V projection
    gemm_tc<1,0><<<dim3(512/64, MB64, 1), 256>>>(p_qk, w_qkv,           b_qkv,        p_qkp, MTOT, 512, Dd, 0);
    gemm_tc<1,0><<<dim3(Dd/64,  MB64, 1), 256>>>(pro,  w_qkv + 2*Dd*Dd, b_qkv + 2*Dd, p_vp,  MTOT, Dd,  Dd, 0);
    // 3. masked MHSA
    attn_kernel<<<dim3((NRr + QT - 1)/QT, Nb), 256, ATTN_SMEM>>>(p_qkp, p_vp, p_mask, p_ctx);
    // 4. out projection, split-K=2 (bias + reduce fused into ln)
    gemm_tc<1,0><<<dim3(Dd/64, MB64, 2), 256>>>(p_ctx, w_ao, nullptr, p_part, MTOT, Dd, Dd, 0);
    // 5. norm1 + mask -> pf1 (raw) + pf1t (tf32 bits)
    ln_kernel<<<MTOT, 256>>>(p_part, 2, b_ao, pro, cm, p_pf1, p_pf1t, 0);
    // 6. dynamic conv params GEMM [2400,32768], PRECVT, output tf32-rounded
    gemm_tc<2,1><<<dim3(PAR/64, MB128, 1), 256>>>((const float*)p_pf1t, (const float*)(p_wc+OFF_WDYN), b_dyn, p_par, MTOT, PAR, Dd, 2);
    // 7. per-instance dynamic conv (re-rounds params: idempotent; writes rounded f2)
    dynconv_tc<<<MTOT, 128, DC_WORDS*4>>>(roi, p_par, p_f2);
    // 8. dyn out projection, K=12544, split-K=8, PRECVT
    gemm_tc<2,1><<<dim3(Dd/64, MB128, 8), 256>>>(p_f2, (const float*)(p_wc+OFF_WDO), nullptr, p_part, MTOT, Dd, Ss*Dd, 0);
    // 9. pf2 = relu(ln(sum_z part + b_do)); pfB = ln(pf1 + pf2) -> raw + tf32
    ln2_kernel<<<MTOT, 256>>>(p_part, 8, b_do, p_pf1, p_pfB, p_pfBt);
    // 10. FFN up + relu, PRECVT, output tf32-rounded
    gemm_tc<2,1><<<dim3(FFf/64, MB128, 1), 256>>>((const float*)p_pfBt, (const float*)(p_wc+OFF_WFF1), b_ff1, p_ffh, MTOT, FFf, Dd, 3);
    // 11. FFN down, K=2048, split-K=4, PRECVT
    gemm_tc<2,1><<<dim3(Dd/64, MB128, 4), 256>>>(p_ffh, (const float*)(p_wc+OFF_WFF2), nullptr, p_part, MTOT, Dd, FFf, 0);
    // 12. norm3 + mask (fc = obj * mask fused)
    ln_kernel<<<MTOT, 256>>>(p_part, 4, b_ff2, p_pfB, cm, p_obj, nullptr, 0);
    // 13. cls tower linear (bias-free), split-K=2
    gemm_tc<1,0><<<dim3(Dd/64, MB64, 2), 256>>>(p_obj, w_cls, nullptr, p_part, MTOT, Dd, Dd, 0);
    // 14. relu(ln(.))
    ln_kernel<<<MTOT, 256>>>(p_part, 2, nullptr, nullptr, nullptr, p_clsf, nullptr, 1);
    // 15. class logits (N=80)
    gemm_tc<1,0><<<dim3((NCc + 63)/64, MB64, 1), 256>>>(p_clsf, w_lg, b_lg, out, MTOT, NCc, Dd, 0);
}

// round 11
// speedup vs baseline: 1.6422x; 1.6422x over previous
#include <cuda_runtime.h>
#include <math.h>

#define Nb   8
#define NRr  300
#define Dd   256
#define Hh   8
#define Ss   49
#define DDd  64
#define FFf  2048
#define NCc  80
#define MTOT (Nb*NRr)          // 2400
#define PAR  32768             // 2*D*DD
#define QT   8

// ---------------- scratch (device globals; no allocation allowed) ----------------
__device__ float g_qk  [MTOT*Dd];
__device__ float g_qkp [MTOT*512];
__device__ float g_vp  [MTOT*Dd];
__device__ float g_ctx [MTOT*Dd];
__device__ float g_pf1 [MTOT*Dd];
__device__ float g_pfB [MTOT*Dd];
__device__ float g_clsf[MTOT*Dd];
__device__ float g_obj [MTOT*Dd];
__device__ float g_ffh [MTOT*FFf];
__device__ float g_params[(size_t)MTOT*PAR];       // 314 MB
__device__ float g_f2  [(size_t)MTOT*Ss*Dd];       // 120 MB
__device__ float g_part[(size_t)8*MTOT*Dd];
__device__ unsigned char g_maskb[Nb*NRr*NRr];

// ---------------- helpers ----------------
__device__ __forceinline__ unsigned f2tf(float x) {
    unsigned u;
    asm("cvt.rna.tf32.f32 %0, %1;" : "=r"(u) : "f"(x));
    return u;
}

__device__ __forceinline__ void mma_tf32(float* d, const unsigned* a, const unsigned* b) {
    asm volatile("mma.sync.aligned.m16n8k8.row.col.f32.tf32.tf32.f32 "
                 "{%0,%1,%2,%3}, {%4,%5,%6,%7}, {%8,%9}, {%0,%1,%2,%3};"
                 : "+f"(d[0]), "+f"(d[1]), "+f"(d[2]), "+f"(d[3])
                 : "r"(a[0]), "r"(a[1]), "r"(a[2]), "r"(a[3]), "r"(b[0]), "r"(b[1]));
}

__device__ __forceinline__ void cpa16(void* smem, const void* g, int sz) {
    unsigned d = (unsigned)__cvta_generic_to_shared(smem);
    asm volatile("cp.async.cg.shared.global [%0], [%1], 16, %2;" :: "r"(d), "l"(g), "r"(sz));
}

__device__ __forceinline__ float blockSum256(float v, float* red) {
#pragma unroll
    for (int o = 16; o; o >>= 1) v += __shfl_down_sync(0xffffffffu, v, o);
    if ((threadIdx.x & 31) == 0) red[threadIdx.x >> 5] = v;
    __syncthreads();
    float s = red[0]+red[1]+red[2]+red[3]+red[4]+red[5]+red[6]+red[7];
    __syncthreads();
    return s;
}

// ---------------- merged: IoU mask + (pro+query) add ----------------
__global__ void init_kernel(const float* __restrict__ bb, const float* __restrict__ cm,
                            unsigned char* __restrict__ mask,
                            const float* __restrict__ pro, const float* __restrict__ query,
                            float* __restrict__ qkout)
{
    int idx = blockIdx.x * blockDim.x + threadIdx.x;
    if (idx < MTOT*Dd) qkout[idx] = pro[idx] + query[idx];
    if (idx < Nb*NRr*NRr) {
        int b = idx / (NRr*NRr);
        int r = idx - b*NRr*NRr;
        int q = r / NRr, k = r - q*NRr;
        const float* bq = bb + (size_t)(b*NRr+q)*4;
        const float* bk = bb + (size_t)(b*NRr+k)*4;
        float areaA = (bq[2]-bq[0])*(bq[3]-bq[1]);
        float areaB = (bk[2]-bk[0])*(bk[3]-bk[1]);
        float ix = fmaxf(fminf(bq[2],bk[2]) - fmaxf(bq[0],bk[0]), 0.f);
        float iy = fmaxf(fminf(bq[3],bk[3]) - fmaxf(bq[1],bk[1]), 0.f);
        float inter = ix*iy;
        float iou = inter / fmaxf(areaA + areaB - inter, 1e-9f);
        float cq = cm[b*NRr+q], ck = cm[b*NRr+k];
        float omask = (iou < 0.5f) ? 1.f : 0.f;
        float val = omask*cq*ck + ((q==k) ? (1.f-cq) : 0.f);
        mask[idx] = (val > 0.f) ? (unsigned char)1 : (unsigned char)0;
    }
}

// ================= tf32 GEMM, 2-stage (R7 baseline, small shapes) ==============
template<int MT>
__global__ void __launch_bounds__(256) gemm_tc(
    const float* __restrict__ A, const float* __restrict__ W,
    const float* __restrict__ bias, float* __restrict__ C,
    int M, int N, int K, int doRelu)
{
    constexpr int BMt = 64*MT;
    __shared__ unsigned As[2][BMt][20];
    __shared__ unsigned Bs[2][64][20];
    int tid  = threadIdx.x;
    int lane = tid & 31;
    int warp = tid >> 5;
    int rowBase = blockIdx.y * BMt;
    int colBase = blockIdx.x * 64;
    int kc   = K / gridDim.z;
    int kbeg = blockIdx.z * kc;
    float* Cp = C + (size_t)blockIdx.z * (size_t)M * (size_t)N;

    int mBase = (warp >> 1) * 16 * MT;
    int nBase = (warp & 1) * 32;
    int gr = lane >> 2, gc = lane & 3;

    float acc[MT][4][4];
#pragma unroll
    for (int a_ = 0; a_ < MT; ++a_)
#pragma unroll
        for (int b_ = 0; b_ < 4; ++b_)
#pragma unroll
            for (int c_ = 0; c_ < 4; ++c_) acc[a_][b_][c_] = 0.f;

    int ar[MT], ak[MT];
#pragma unroll
    for (int c = 0; c < MT; ++c) { int u = tid + c*256; ar[c] = u >> 2; ak[c] = (u & 3) * 4; }
    int br = tid >> 2, bk = (tid & 3) * 4;

    int nIter = kc / 16;

    {
#pragma unroll
        for (int c = 0; c < MT; ++c) {
            int r = rowBase + ar[c];
            int rc = (r < M) ? r : (M - 1);
            cpa16(&As[0][ar[c]][ak[c]], A + (size_t)rc*K + kbeg + ak[c], (r < M) ? 16 : 0);
        }
        int n = colBase + br;
        int ncl = (n < N) ? n : (N - 1);
        cpa16(&Bs[0][br][bk], W + (size_t)ncl*K + kbeg + bk, (n < N) ? 16 : 0);
        asm volatile("cp.async.commit_group;");
    }

    for (int i = 0; i < nIter; ++i) {
        if (i + 1 < nIter) {
            int k0 = kbeg + (i+1)*16;
            int nb = (i+1) & 1;
#pragma unroll
            for (int c = 0; c < MT; ++c) {
                int r = rowBase + ar[c];
                int rc = (r < M) ? r : (M - 1);
                cpa16(&As[nb][ar[c]][ak[c]], A + (size_t)rc*K + k0 + ak[c], (r < M) ? 16 : 0);
            }
            int n = colBase + br;
            int ncl = (n < N) ? n : (N - 1);
            cpa16(&Bs[nb][br][bk], W + (size_t)ncl*K + k0 + bk, (n < N) ? 16 : 0);
            asm volatile("cp.async.commit_group;");
            asm volatile("cp.async.wait_group 1;");
        } else {
            asm volatile("cp.async.wait_group 0;");
        }
        __syncthreads();
        int buf = i & 1;
#pragma unroll
        for (int ks = 0; ks < 16; ks += 8) {
            unsigned a[MT][4], b[4][2];
#pragma unroll
            for (int mt = 0; mt < MT; ++mt) {
                int row = mBase + mt*16;
                a[mt][0] = f2tf(__uint_as_float(As[buf][row+gr  ][ks+gc  ]));
                a[mt][1] = f2tf(__uint_as_float(As[buf][row+gr+8][ks+gc  ]));
                a[mt][2] = f2tf(__uint_as_float(As[buf][row+gr  ][ks+4+gc]));
                a[mt][3] = f2tf(__uint_as_float(As[buf][row+gr+8][ks+4+gc]));
            }
#pragma unroll
            for (int nt = 0; nt < 4; ++nt) {
                int col = nBase + nt*8;
                b[nt][0] = f2tf(__uint_as_float(Bs[buf][col+gr][ks+gc  ]));
                b[nt][1] = f2tf(__uint_as_float(Bs[buf][col+gr][ks+4+gc]));
            }
#pragma unroll
            for (int mt = 0; mt < MT; ++mt)
#pragma unroll
                for (int nt = 0; nt < 4; ++nt)
                    mma_tf32(acc[mt][nt], a[mt], b[nt]);
        }
        __syncthreads();
    }

#pragma unroll
    for (int mt = 0; mt < MT; ++mt) {
#pragma unroll
        for (int nt = 0; nt < 4; ++nt) {
            int c = colBase + nBase + nt*8 + gc*2;
            if (c >= N) continue;
            float bx = bias ? bias[c]   : 0.f;
            float by = bias ? bias[c+1] : 0.f;
            int r0 = rowBase + mBase + mt*16 + gr;
            if (r0 < M) {
                float x = acc[mt][nt][0] + bx, y = acc[mt][nt][1] + by;
                if (doRelu) { x = fmaxf(x,0.f); y = fmaxf(y,0.f); }
                *(float2*)(Cp + (size_t)r0*N + c) = make_float2(x, y);
            }
            int r1 = r0 + 8;
            if (r1 < M) {
                float x = acc[mt][nt][2] + bx, y = acc[mt][nt][3] + by;
                if (doRelu) { x = fmaxf(x,0.f); y = fmaxf(y,0.f); }
                *(float2*)(Cp + (size_t)r1*N + c) = make_float2(x, y);
            }
        }
    }
}

// ================= tf32 GEMM, BM=128 x BN=128, warp tile 32x64 (big shapes) =====
// Same 2-stage loop discipline; N must be divisible by 128.
__global__ void __launch_bounds__(256) gemm_big(
    const float* __restrict__ A, const float* __restrict__ W,
    const float* __restrict__ bias, float* __restrict__ C,
    int M, int N, int K, int doRelu)
{
    __shared__ unsigned As[2][128][20];
    __shared__ unsigned Bs[2][128][20];
    int tid  = threadIdx.x;
    int lane = tid & 31;
    int warp = tid >> 5;
    int rowBase = blockIdx.y * 128;
    int colBase = blockIdx.x * 128;
    int kc   = K / gridDim.z;
    int kbeg = blockIdx.z * kc;
    float* Cp = C + (size_t)blockIdx.z * (size_t)M * (size_t)N;

    int mBase = (warp >> 1) * 32;     // 4 row groups of 32
    int nBase = (warp & 1) * 64;      // 2 col groups of 64
    int gr = lane >> 2, gc = lane & 3;

    float acc[2][8][4];
#pragma unroll
    for (int a_ = 0; a_ < 2; ++a_)
#pragma unroll
        for (int b_ = 0; b_ < 8; ++b_)
#pragma unroll
            for (int c_ = 0; c_ < 4; ++c_) acc[a_][b_][c_] = 0.f;

    // staging: A and B each 128 rows x 16 words -> 512 cpa16 -> 2 per thread each
    int sr[2], sk[2];
#pragma unroll
    for (int c = 0; c < 2; ++c) { int u = tid + c*256; sr[c] = u >> 2; sk[c] = (u & 3) * 4; }

    int nIter = kc / 16;

    {
#pragma unroll
        for (int c = 0; c < 2; ++c) {
            int r = rowBase + sr[c];
            int rc = (r < M) ? r : (M - 1);
            cpa16(&As[0][sr[c]][sk[c]], A + (size_t)rc*K + kbeg + sk[c], (r < M) ? 16 : 0);
            int n = colBase + sr[c];
            cpa16(&Bs[0][sr[c]][sk[c]], W + (size_t)n*K + kbeg + sk[c], 16);
        }
        asm volatile("cp.async.commit_group;");
    }

    for (int i = 0; i < nIter; ++i) {
        if (i + 1 < nIter) {
            int k0 = kbeg + (i+1)*16;
            int nb = (i+1) & 1;
#pragma unroll
            for (int c = 0; c < 2; ++c) {
                int r = rowBase + sr[c];
                int rc = (r < M) ? r : (M - 1);
                cpa16(&As[nb][sr[c]][sk[c]], A + (size_t)rc*K + k0 + sk[c], (r < M) ? 16 : 0);
                int n = colBase + sr[c];
                cpa16(&Bs[nb][sr[c]][sk[c]], W + (size_t)n*K + k0 + sk[c], 16);
            }
            asm volatile("cp.async.commit_group;");
            asm volatile("cp.async.wait_group 1;");
        } else {
            asm volatile("cp.async.wait_group 0;");
        }
        __syncthreads();
        int buf = i & 1;
#pragma unroll
        for (int ks = 0; ks < 16; ks += 8) {
            unsigned a[2][4], b[8][2];
#pragma unroll
            for (int mt = 0; mt < 2; ++mt) {
                int row = mBase + mt*16;
                a[mt][0] = f2tf(__uint_as_float(As[buf][row+gr  ][ks+gc  ]));
                a[mt][1] = f2tf(__uint_as_float(As[buf][row+gr+8][ks+gc  ]));
                a[mt][2] = f2tf(__uint_as_float(As[buf][row+gr  ][ks+4+gc]));
                a[mt][3] = f2tf(__uint_as_float(As[buf][row+gr+8][ks+4+gc]));
            }
#pragma unroll
            for (int nt = 0; nt < 8; ++nt) {
                int col = nBase + nt*8;
                b[nt][0] = f2tf(__uint_as_float(Bs[buf][col+gr][ks+gc  ]));
                b[nt][1] = f2tf(__uint_as_float(Bs[buf][col+gr][ks+4+gc]));
            }
#pragma unroll
            for (int mt = 0; mt < 2; ++mt)
#pragma unroll
                for (int nt = 0; nt < 8; ++nt)
                    mma_tf32(acc[mt][nt], a[mt], b[nt]);
        }
        __syncthreads();
    }

#pragma unroll
    for (int mt = 0; mt < 2; ++mt) {
#pragma unroll
        for (int nt = 0; nt < 8; ++nt) {
            int c = colBase + nBase + nt*8 + gc*2;
            float bx = bias ? bias[c]   : 0.f;
            float by = bias ? bias[c+1] : 0.f;
            int r0 = rowBase + mBase + mt*16 + gr;
            if (r0 < M) {
                float x = acc[mt][nt][0] + bx, y = acc[mt][nt][1] + by;
                if (doRelu) { x = fmaxf(x,0.f); y = fmaxf(y,0.f); }
                *(float2*)(Cp + (size_t)r0*N + c) = make_float2(x, y);
            }
            int r1 = r0 + 8;
            if (r1 < M) {
                float x = acc[mt][nt][2] + bx, y = acc[mt][nt][3] + by;
                if (doRelu) { x = fmaxf(x,0.f); y = fmaxf(y,0.f); }
                *(float2*)(Cp + (size_t)r1*N + c) = make_float2(x, y);
            }
        }
    }
}

// ---------------- masked MHSA: 8 queries per block, warp = head (R7) -----------
#define ATTN_SMEM ((QT*256 + Hh*QT*NRr) * 4)
__global__ void __launch_bounds__(256) attn_kernel(
    const float* __restrict__ qkp, const float* __restrict__ vp,
    const unsigned char* __restrict__ mask, float* __restrict__ ctx)
{
    extern __shared__ float smf[];
    float* sq = smf;
    float* sc = smf + QT*256;
    int b  = blockIdx.y;
    int q0 = blockIdx.x * QT;
    int tid = threadIdx.x, w = tid >> 5, lane = tid & 31;

#pragma unroll
    for (int j = 0; j < QT; ++j) {
        int q = q0 + j; if (q >= NRr) q = NRr - 1;
        sq[j*256 + tid] = qkp[(size_t)(b*NRr + q)*512 + tid];
    }
    __syncthreads();

    const float scale = 0.17677669529663687f;
    float* scw = sc + w*QT*NRr;
    const unsigned char* mbase = mask + (size_t)b*NRr*NRr;

    for (int k = lane; k < NRr; k += 32) {
        const float4* kr = (const float4*)(qkp + ((size_t)(b*NRr + k))*512 + 256 + w*32);
        float4 kv[8];
#pragma unroll
        for (int u = 0; u < 8; ++u) kv[u] = kr[u];
#pragma unroll
        for (int j = 0; j < QT; ++j) {
            const float* sqr = sq + j*256 + w*32;
            float s = 0.f;
#pragma unroll
            for (int u = 0; u < 8; ++u)
                s += sqr[u*4+0]*kv[u].x + sqr[u*4+1]*kv[u].y + sqr[u*4+2]*kv[u].z + sqr[u*4+3]*kv[u].w;
            s *= scale;
            int q = q0 + j;
            if (q < NRr && mbase[(size_t)q*NRr + k]) s = -1e9f;
            scw[j*NRr + k] = s;
        }
    }
    __syncwarp();

    float inv[QT];
#pragma unroll
    for (int j = 0; j < QT; ++j) {
        float mx = -1e30f;
        for (int k = lane; k < NRr; k += 32) mx = fmaxf(mx, scw[j*NRr + k]);
#pragma unroll
        for (int o = 16; o; o >>= 1) mx = fmaxf(mx, __shfl_xor_sync(0xffffffffu, mx, o));
        float sum = 0.f;
        for (int k = lane; k < NRr; k += 32) {
            float e = expf(scw[j*NRr + k] - mx);
            scw[j*NRr + k] = e;
            sum += e;
        }
#pragma unroll
        for (int o = 16; o; o >>= 1) sum += __shfl_xor_sync(0xffffffffu, sum, o);
        inv[j] = 1.f / sum;
    }
    __syncwarp();

    float acc[QT];
#pragma unroll
    for (int j = 0; j < QT; ++j) acc[j] = 0.f;
#pragma unroll 4
    for (int k = 0; k < NRr; ++k) {
        float vv = vp[((size_t)(b*NRr + k))*Dd + w*32 + lane];
#pragma unroll
        for (int j = 0; j < QT; ++j) acc[j] += scw[j*NRr + k] * vv;
    }
#pragma unroll
    for (int j = 0; j < QT; ++j) {
        int q = q0 + j;
        if (q < NRr) ctx[(size_t)(b*NRr + q)*Dd + w*32 + lane] = acc[j] * inv[j];
    }
}

// ---------------- LayerNorm (D=256); X may be nz split-K slices ----------------
__global__ void ln_kernel(const float* __restrict__ X, int nz, const float* __restrict__ bias,
                          const float* __restrict__ R, const float* __restrict__ mrow,
                          float* __restrict__ out, int doRelu)
{
    __shared__ float red[8];
    int i = blockIdx.x, t = threadIdx.x;
    float x = X[(size_t)i*Dd + t];
    for (int z = 1; z < nz; ++z) x += X[(size_t)z*MTOT*Dd + (size_t)i*Dd + t];
    if (bias) x += bias[t];
    if (R) x += R[(size_t)i*Dd + t];
    float m  = blockSum256(x, red) * (1.f/Dd);
    float dv = x - m;
    float var = blockSum256(dv*dv, red) * (1.f/Dd);
    float y = dv * rsqrtf(var + 1e-5f);
    if (doRelu) y = fmaxf(y, 0.f);
    if (mrow) y *= mrow[i];
    out[(size_t)i*Dd + t] = y;
}

// ---------------- double LN: out = ln( relu(ln(sum_z X_z + bias)) + P ) ----------
__global__ void ln2_kernel(const float* __restrict__ X, int nz, const float* __restrict__ bias,
                           const float* __restrict__ P, float* __restrict__ out)
{
    __shared__ float red[8];
    int i = blockIdx.x, t = threadIdx.x;
    float x = X[(size_t)i*Dd + t];
    for (int z = 1; z < nz; ++z) x += X[(size_t)z*MTOT*Dd + (size_t)i*Dd + t];
    if (bias) x += bias[t];
    float m  = blockSum256(x, red) * (1.f/Dd);
    float dv = x - m;
    float var = blockSum256(dv*dv, red) * (1.f/Dd);
    float y = fmaxf(dv * rsqrtf(var + 1e-5f), 0.f);
    float z2 = y + P[(size_t)i*Dd + t];
    m  = blockSum256(z2, red) * (1.f/Dd);
    dv = z2 - m;
    var = blockSum256(dv*dv, red) * (1.f/Dd);
    out[(size_t)i*Dd + t] = dv * rsqrtf(var + 1e-5f);
}

// ================= DynamicConv v2 (R7 version) ===================================
#define DC_U    0
#define DC_F1   4608
#define DC_F2R  (DC_F1 + 4608)
#define DC_WORDS (DC_F2R + 49*264)

__global__ void __launch_bounds__(128) dynconv_tc(
    const float* __restrict__ roi, const float* __restrict__ params,
    float* __restrict__ f2out)
{
    extern __shared__ unsigned sm[];
    unsigned* Asm = sm + DC_U;
    unsigned* Bsm = sm + DC_U + 32*72;
    unsigned* Bs2 = sm + DC_U;
    unsigned* f1t = sm + DC_F1;
    float*    f2r = (float*)(sm + DC_F2R);

    int i    = blockIdx.x;
    int tid  = threadIdx.x;
    int lane = tid & 31;
    int warp = tid >> 5;
    int gr = lane >> 2, gc = lane & 3;
    int rowW = warp * 16;

    const float* p1 = params + (size_t)i * PAR;
    const float* p2 = p1 + Dd*DDd;

    int sA = tid >> 3;
    int d4A = (tid & 7) * 4;
    int dB = tid >> 4;
    int e4B = (tid & 15) * 4;

    float4 rA[4]; float4 rB[4];
#pragma unroll
    for (int p = 0; p < 4; ++p) {
        int s = p*16 + sA;
        rA[p] = (s < Ss) ? *(const float4*)(roi + ((size_t)s*MTOT + i)*Dd + 0 + d4A)
                         : make_float4(0.f,0.f,0.f,0.f);
        rB[p] = *(const float4*)(p1 + (size_t)(0 + p*8 + dB)*DDd + e4B);
    }

    float acc1[8][4];
#pragma unroll
    for (int a_ = 0; a_ < 8; ++a_)
#pragma unroll
        for (int c_ = 0; c_ < 4; ++c_) acc1[a_][c_] = 0.f;

    for (int dc = 0; dc < Dd; dc += 32) {
        __syncthreads();
#pragma unroll
        for (int p = 0; p < 4; ++p) {
            Asm[(d4A+0)*72 + p*16+sA] = f2tf(rA[p].x);
            Asm[(d4A+1)*72 + p*16+sA] = f2tf(rA[p].y);
            Asm[(d4A+2)*72 + p*16+sA] = f2tf(rA[p].z);
            Asm[(d4A+3)*72 + p*16+sA] = f2tf(rA[p].w);
            int d = p*8 + dB;
            Bsm[d*72 + e4B+0] = f2tf(rB[p].x);
            Bsm[d*72 + e4B+1] = f2tf(rB[p].y);
            Bsm[d*72 + e4B+2] = f2tf(rB[p].z);
            Bsm[d*72 + e4B+3] = f2tf(rB[p].w);
        }
        __syncthreads();
        if (dc + 32 < Dd) {
            int dn = dc + 32;
#pragma unroll
            for (int p = 0; p < 4; ++p) {
                int s = p*16 + sA;
                rA[p] = (s < Ss) ? *(const float4*)(roi + ((size_t)s*MTOT + i)*Dd + dn + d4A)
                                 : make_float4(0.f,0.f,0.f,0.f);
                rB[p] = *(const float4*)(p1 + (size_t)(dn + p*8 + dB)*DDd + e4B);
            }
        }
#pragma unroll
        for (int ks = 0; ks < 32; ks += 8) {
            unsigned a[4], b[8][2];
            a[0] = Asm[(ks+gc  )*72 + rowW+gr  ];
            a[1] = Asm[(ks+gc  )*72 + rowW+gr+8];
            a[2] = Asm[(ks+4+gc)*72 + rowW+gr  ];
            a[3] = Asm[(ks+4+gc)*72 + rowW+gr+8];
#pragma unroll
            for (int nt = 0; nt < 8; ++nt) {
                b[nt][0] = Bsm[(ks+gc  )*72 + nt*8+gr];
                b[nt][1] = Bsm[(ks+4+gc)*72 + nt*8+gr];
            }
#pragma unroll
            for (int nt = 0; nt < 8; ++nt) mma_tf32(acc1[nt], a, b[nt]);
        }
    }
    {
        float s0 = 0.f, s1 = 0.f;
#pragma unroll
        for (int nt = 0; nt < 8; ++nt) { s0 += acc1[nt][0]+acc1[nt][1]; s1 += acc1[nt][2]+acc1[nt][3]; }
        s0 += __shfl_xor_sync(0xffffffffu, s0, 1); s0 += __shfl_xor_sync(0xffffffffu, s0, 2);
        s1 += __shfl_xor_sync(0xffffffffu, s1, 1); s1 += __shfl_xor_sync(0xffffffffu, s1, 2);
        float m0 = s0 * (1.f/DDd), m1 = s1 * (1.f/DDd);
        float v0 = 0.f, v1 = 0.f;
#pragma unroll
        for (int nt = 0; nt < 8; ++nt) {
            float d0 = acc1[nt][0]-m0, d1 = acc1[nt][1]-m0;
            float d2 = acc1[nt][2]-m1, d3 = acc1[nt][3]-m1;
            v0 += d0*d0 + d1*d1; v1 += d2*d2 + d3*d3;
        }
        v0 += __shfl_xor_sync(0xffffffffu, v0, 1); v0 += __shfl_xor_sync(0xffffffffu, v0, 2);
        v1 += __shfl_xor_sync(0xffffffffu, v1, 1); v1 += __shfl_xor_sync(0xffffffffu, v1, 2);
        float r0f = rsqrtf(v0*(1.f/DDd) + 1e-5f);
        float r1f = rsqrtf(v1*(1.f/DDd) + 1e-5f);
        int sr0 = rowW + gr, sr1 = sr0 + 8;
#pragma unroll
        for (int nt = 0; nt < 8; ++nt) {
            int e = nt*8 + gc*2;
            f1t[(e  )*72 + sr0] = f2tf(fmaxf((acc1[nt][0]-m0)*r0f, 0.f));
            f1t[(e+1)*72 + sr0] = f2tf(fmaxf((acc1[nt][1]-m0)*r0f, 0.f));
            f1t[(e  )*72 + sr1] = f2tf(fmaxf((acc1[nt][2]-m1)*r1f, 0.f));
            f1t[(e+1)*72 + sr1] = f2tf(fmaxf((acc1[nt][3]-m1)*r1f, 0.f));
        }
    }

    float4 rC[8];
#pragma unroll
    for (int p = 0; p < 8; ++p)
        rC[p] = *(const float4*)(p2 + (size_t)(p*8 + dB)*Dd + 0 + e4B);

    for (int nc = 0; nc < Dd; nc += 64) {
        __syncthreads();
#pragma unroll
        for (int p = 0; p < 8; ++p) {
            int e = p*8 + dB;
            Bs2[e*72 + e4B+0] = f2tf(rC[p].x);
            Bs2[e*72 + e4B+1] = f2tf(rC[p].y);
            Bs2[e*72 + e4B+2] = f2tf(rC[p].z);
            Bs2[e*72 + e4B+3] = f2tf(rC[p].w);
        }
        __syncthreads();
        if (nc + 64 < Dd) {
            int nn = nc + 64;
#pragma unroll
            for (int p = 0; p < 8; ++p)
                rC[p] = *(const float4*)(p2 + (size_t)(p*8 + dB)*Dd + nn + e4B);
        }
        float acc2[8][4];
#pragma unroll
        for (int a_ = 0; a_ < 8; ++a_)
#pragma unroll
            for (int c_ = 0; c_ < 4; ++c_) acc2[a_][c_] = 0.f;
#pragma unroll
        for (int ks = 0; ks < 64; ks += 8) {
            unsigned a[4], b[8][2];
            a[0] = f1t[(ks+gc  )*72 + rowW+gr  ];
            a[1] = f1t[(ks+gc  )*72 + rowW+gr+8];
            a[2] = f1t[(ks+4+gc)*72 + rowW+gr  ];
            a[3] = f1t[(ks+4+gc)*72 + rowW+gr+8];
#pragma unroll
            for (int nt = 0; nt < 8; ++nt) {
                b[nt][0] = Bs2[(ks+gc  )*72 + nt*8+gr];
                b[nt][1] = Bs2[(ks+4+gc)*72 + nt*8+gr];
            }
#pragma unroll
            for (int nt = 0; nt < 8; ++nt) mma_tf32(acc2[nt], a, b[nt]);
        }
        int sr0 = rowW + gr, sr1 = sr0 + 8;
#pragma unroll
        for (int nt = 0; nt < 8; ++nt) {
            int c = nc + nt*8 + gc*2;
            if (sr0 < Ss) *(float2*)(f2r + sr0*264 + c) = make_float2(acc2[nt][0], acc2[nt][1]);
            if (sr1 < Ss) *(float2*)(f2r + sr1*264 + c) = make_float2(acc2[nt][2], acc2[nt][3]);
        }
    }
    __syncthreads();

    for (int s = warp; s < Ss; s += 4) {
        float v[8];
        float sum = 0.f;
#pragma unroll
        for (int j = 0; j < 8; ++j) { v[j] = f2r[s*264 + lane + 32*j]; sum += v[j]; }
#pragma unroll
        for (int o = 16; o; o >>= 1) sum += __shfl_xor_sync(0xffffffffu, sum, o);
        float m = sum * (1.f/Dd);
        float var = 0.f;
#pragma unroll
        for (int j = 0; j < 8; ++j) { float d = v[j]-m; var += d*d; }
#pragma unroll
        for (int o = 16; o; o >>= 1) var += __shfl_xor_sync(0xffffffffu, var, o);
        float rs = rsqrtf(var*(1.f/Dd) + 1e-5f);
        float* op = f2out + ((size_t)i*Ss + s)*Dd;
#pragma unroll
        for (int j = 0; j < 8; ++j)
            op[lane + 32*j] = fmaxf((v[j]-m)*rs, 0.f);
    }
}

// ---------------- host side ----------------
static float* symaddr(const void* sym) { void* p = nullptr; cudaGetSymbolAddress(&p, sym); return (float*)p; }

extern "C" void kernel_launch(void* const* d_in, const int* in_sizes, int n_in,
                              void* d_out, int out_size)
{
    const float* bboxes = (const float*)d_in[0];
    const float* pro    = (const float*)d_in[1];
    const float* roi    = (const float*)d_in[2];
    const float* query  = (const float*)d_in[3];
    const float* cm     = (const float*)d_in[4];
    const float* w_qkv  = (const float*)d_in[5];
    const float* b_qkv  = (const float*)d_in[6];
    const float* w_ao   = (const float*)d_in[7];
    const float* b_ao   = (const float*)d_in[8];
    const float* w_dyn  = (const float*)d_in[9];
    const float* b_dyn  = (const float*)d_in[10];
    const float* w_do   = (const float*)d_in[11];
    const float* b_do   = (const float*)d_in[12];
    const float* w_ff1  = (const float*)d_in[13];
    const float* b_ff1  = (const float*)d_in[14];
    const float* w_ff2  = (const float*)d_in[15];
    const float* b_ff2  = (const float*)d_in[16];
    const float* w_cls  = (const float*)d_in[17];
    const float* w_lg   = (const float*)d_in[18];
    const float* b_lg   = (const float*)d_in[19];
    float* out = (float*)d_out;

    float* p_qk   = symaddr(g_qk);
    float* p_qkp  = symaddr(g_qkp);
    float* p_vp   = symaddr(g_vp);
    float* p_ctx  = symaddr(g_ctx);
    float* p_pf1  = symaddr(g_pf1);
    float* p_pfB  = symaddr(g_pfB);
    float* p_obj  = symaddr(g_obj);
    float* p_clsf = symaddr(g_clsf);
    float* p_ffh  = symaddr(g_ffh);
    float* p_par  = symaddr(g_params);
    float* p_f2   = symaddr(g_f2);
    float* p_part = symaddr(g_part);
    unsigned char* p_mask; { void* v; cudaGetSymbolAddress(&v, g_maskb); p_mask = (unsigned char*)v; }

    static int smem_set = 0;
    if (!smem_set) {
        cudaFuncSetAttribute(dynconv_tc, cudaFuncAttributeMaxDynamicSharedMemorySize, DC_WORDS * 4);
        cudaFuncSetAttribute(attn_kernel, cudaFuncAttributeMaxDynamicSharedMemorySize, ATTN_SMEM);
        smem_set = 1;
    }

    const int MB128 = (MTOT + 127) / 128;   // 19
    const int MB64  = (MTOT + 63) / 64;     // 38

    // 1. IoU mask + (pro+query) merged
    init_kernel<<<(Nb*NRr*NRr + 255)/256, 256>>>(bboxes, cm, p_mask, pro, query, p_qk);
    // 2. merged Q|K projection (N=512) and V projection
    gemm_tc<1><<<dim3(512/64, MB64, 1), 256>>>(p_qk, w_qkv,           b_qkv,        p_qkp, MTOT, 512, Dd, 0);
    gemm_tc<1><<<dim3(Dd/64,  MB64, 1), 256>>>(pro,  w_qkv + 2*Dd*Dd, b_qkv + 2*Dd, p_vp,  MTOT, Dd,  Dd, 0);
    // 3. masked MHSA
    attn_kernel<<<dim3((NRr + QT - 1)/QT, Nb), 256, ATTN_SMEM>>>(p_qkp, p_vp, p_mask, p_ctx);
    // 4. out projection, split-K=2 (bias + reduce fused into ln)
    gemm_tc<1><<<dim3(Dd/64, MB64, 2), 256>>>(p_ctx, w_ao, nullptr, p_part, MTOT, Dd, Dd, 0);
    // 5. norm1 + mask
    ln_kernel<<<MTOT, 256>>>(p_part, 2, b_ao, pro, cm, p_pf1, 0);
    // 6. dynamic conv params GEMM [2400,32768]  (BIG tile)
    gemm_big<<<dim3(PAR/128, MB128, 1), 256>>>(p_pf1, w_dyn, b_dyn, p_par, MTOT, PAR, Dd, 0);
    // 7. per-instance dynamic conv
    dynconv_tc<<<MTOT, 128, DC_WORDS*4>>>(roi, p_par, p_f2);
    // 8. dyn out projection, K=12544, split-K=8 (BIG tile; reduce fused into ln2)
    gemm_big<<<dim3(Dd/128, MB128, 8), 256>>>(p_f2, w_do, nullptr, p_part, MTOT, Dd, Ss*Dd, 0);
    // 9. pf2 = relu(ln(sum_z part + b_do)); pfB = ln(pf1 + pf2)
    ln2_kernel<<<MTOT, 256>>>(p_part, 8, b_do, p_pf1, p_pfB);
    // 10. FFN up + relu (BIG tile)
    gemm_big<<<dim3(FFf/128, MB128, 1), 256>>>(p_pfB, w_ff1, b_ff1, p_ffh, MTOT, FFf, Dd, 1);
    // 11. FFN down, K=2048, split-K=4 (BIG tile; reduce fused into ln)
    gemm_big<<<dim3(Dd/128, MB128, 4), 256>>>(p_ffh, w_ff2, nullptr, p_part, MTOT, Dd, FFf, 0);
    // 12. norm3 + mask (fc = obj * mask fused)
    ln_kernel<<<MTOT, 256>>>(p_part, 4, b_ff2, p_pfB, cm, p_obj, 0);
    // 13. cls tower linear (bias-free), split-K=2 (reduce fused into ln)
    gemm_tc<1><<<dim3(Dd/64, MB64, 2), 256>>>(p_obj, w_cls, nullptr, p_part, MTOT, Dd, Dd, 0);
    // 14. relu(ln(.))
    ln_kernel<<<MTOT, 256>>>(p_part, 2, nullptr, nullptr, nullptr, p_clsf, 1);
    // 15. class logits (N=80)
    gemm_tc<1><<<dim3((NCc + 63)/64, MB64, 1), 256>>>(p_clsf, w_lg, b_lg, out, MTOT, NCc, Dd, 0);
}